// round 15
// baseline (speedup 1.0000x reference)
#include <cuda_runtime.h>
#include <cuda_bf16.h>
#include <cuda_fp16.h>
#include <math.h>
#include <stdint.h>

// Problem constants
#define BB 8
#define LL 1024
#define DD 256
#define EE 8
#define HH 1024
#define LMAXC 512
#define NTOK (BB*DD)   // 2048 tokens (b,d)

// ---------------- scratch (__device__ globals; no allocations) ----------------
__device__ float g_xt  [BB*DD*LL];        // x transposed [B][D][L] (for k_down)
__device__ float g_bufA[BB*DD*LL];        // conv2 fp32 output (router input)
__device__ float g_h1  [EE*NTOK*HH];      // h3 fp32 (combine input)
__device__ int   g_cnt [EE];
__device__ int   g_idx [EE*NTOK];
__device__ int   g_tok_e[NTOK*2];
__device__ int   g_tok_p[NTOK*2];
__device__ float g_tok_g[NTOK*2];
// conv path: bf16 split ping-pong [b][l][din/2]
__device__ uint32_t g_wsp_hi[3*3*256*128];   // [layer][tap][dout][din/2]
__device__ uint32_t g_wsp_lo[3*3*256*128];
__device__ uint32_t g_sp0_hi[BB*LL*128];
__device__ uint32_t g_sp0_lo[BB*LL*128];
__device__ uint32_t g_sp1_hi[BB*LL*128];
__device__ uint32_t g_sp1_lo[BB*LL*128];
// expert path: fp16 split activations
__device__ uint32_t g_xes_hi[EE*NTOK*256];   // [e][i][LMAXC/2]
__device__ uint32_t g_xes_lo[EE*NTOK*256];
__device__ uint32_t g_h1s_hi[EE*NTOK*512];   // [e][i][HH/2]
__device__ uint32_t g_h1s_lo[EE*NTOK*512];
__device__ uint32_t g_h2s_hi[EE*NTOK*512];
__device__ uint32_t g_h2s_lo[EE*NTOK*512];

__constant__ int c_len [EE] = {512,341,256,204,170,146,128,113};
__constant__ int c_nc32[EE] = {16,11,8,7,6,5,4,4};   // ceil(len/32) K-chunks, layer 1

__device__ __forceinline__ float gelu_f(float x){
    return 0.5f * x * (1.0f + erff(x * 0.70710678118654752f));
}

// ---- bf16 split (conv/router path) ----
__device__ __forceinline__ void cvt2_split(float a, float b, uint32_t& hp, uint32_t& lp){
    __nv_bfloat16 h0 = __float2bfloat16_rn(a);
    __nv_bfloat16 h1 = __float2bfloat16_rn(b);
    __nv_bfloat16 l0 = __float2bfloat16_rn(a - __bfloat162float(h0));
    __nv_bfloat16 l1 = __float2bfloat16_rn(b - __bfloat162float(h1));
    hp = (uint32_t)__bfloat16_as_ushort(h0) | ((uint32_t)__bfloat16_as_ushort(h1) << 16);
    lp = (uint32_t)__bfloat16_as_ushort(l0) | ((uint32_t)__bfloat16_as_ushort(l1) << 16);
}
// ---- fp16 split (expert path) ----
__device__ __forceinline__ void cvt2_split_h(float a, float b, uint32_t& hp, uint32_t& lp){
    __half h0 = __float2half_rn(a);
    __half h1 = __float2half_rn(b);
    __half l0 = __float2half_rn(a - __half2float(h0));
    __half l1 = __float2half_rn(b - __half2float(h1));
    hp = (uint32_t)__half_as_ushort(h0) | ((uint32_t)__half_as_ushort(h1) << 16);
    lp = (uint32_t)__half_as_ushort(l0) | ((uint32_t)__half_as_ushort(l1) << 16);
}
__device__ __forceinline__ void cvt4_hi_h(float4 v, uint32_t* hp){
    __half h0 = __float2half_rn(v.x);
    __half h1 = __float2half_rn(v.y);
    __half h2 = __float2half_rn(v.z);
    __half h3 = __float2half_rn(v.w);
    hp[0] = (uint32_t)__half_as_ushort(h0) | ((uint32_t)__half_as_ushort(h1) << 16);
    hp[1] = (uint32_t)__half_as_ushort(h2) | ((uint32_t)__half_as_ushort(h3) << 16);
}

__device__ __forceinline__ void mma16816_bf(float* d, const uint32_t* a, const uint32_t* b){
    asm volatile(
        "mma.sync.aligned.m16n8k16.row.col.f32.bf16.bf16.f32 "
        "{%0,%1,%2,%3}, {%4,%5,%6,%7}, {%8,%9}, {%0,%1,%2,%3};"
        : "+f"(d[0]), "+f"(d[1]), "+f"(d[2]), "+f"(d[3])
        : "r"(a[0]), "r"(a[1]), "r"(a[2]), "r"(a[3]), "r"(b[0]), "r"(b[1]));
}
__device__ __forceinline__ void mma16816_h(float* d, const uint32_t* a, const uint32_t* b){
    asm volatile(
        "mma.sync.aligned.m16n8k16.row.col.f32.f16.f16.f32 "
        "{%0,%1,%2,%3}, {%4,%5,%6,%7}, {%8,%9}, {%0,%1,%2,%3};"
        : "+f"(d[0]), "+f"(d[1]), "+f"(d[2]), "+f"(d[3])
        : "r"(a[0]), "r"(a[1]), "r"(a[2]), "r"(a[3]), "r"(b[0]), "r"(b[1]));
}
// 4-fragment shared load
#define LDMX4(r, a) \
    asm volatile("ldmatrix.sync.aligned.m8n8.x4.shared.b16 {%0,%1,%2,%3}, [%4];" \
        : "=r"((r)[0]), "=r"((r)[1]), "=r"((r)[2]), "=r"((r)[3]) : "r"(a))
// cp.async: 16B global->shared, optional zero-fill via src-size
#define CP_A16(d, s)     asm volatile("cp.async.cg.shared.global [%0], [%1], 16;" :: "r"(d), "l"(s))
#define CP_A16S(d, s, z) asm volatile("cp.async.cg.shared.global [%0], [%1], 16, %2;" :: "r"(d), "l"(s), "r"(z))
#define CP_COMMIT()      asm volatile("cp.async.commit_group;" ::: "memory")
#define CP_WAIT0()       asm volatile("cp.async.wait_group 0;" ::: "memory")

// pointer selectors (host can't take addresses of __device__ globals)
__device__ __forceinline__ const uint32_t* spin_hi(int s){ return s ? g_sp1_hi : g_sp0_hi; }
__device__ __forceinline__ const uint32_t* spin_lo(int s){ return s ? g_sp1_lo : g_sp0_lo; }
__device__ __forceinline__ uint32_t* spout_hi(int s){ return s ? g_sp1_hi : g_sp0_hi; }
__device__ __forceinline__ uint32_t* spout_lo(int s){ return s ? g_sp1_lo : g_sp0_lo; }
__device__ __forceinline__ const uint32_t* asel_hi(int s){ return s==0 ? g_xes_hi : (s==1 ? g_h1s_hi : g_h2s_hi); }
__device__ __forceinline__ const uint32_t* asel_lo(int s){ return s==0 ? g_xes_lo : (s==1 ? g_h1s_lo : g_h2s_lo); }
__device__ __forceinline__ uint32_t* osel_hi(int s){ return s==1 ? g_h1s_hi : g_h2s_hi; }
__device__ __forceinline__ uint32_t* osel_lo(int s){ return s==1 ? g_h1s_lo : g_h2s_lo; }

// ---------------- init ----------------
__global__ void k_init(){
    if (threadIdx.x < EE) g_cnt[threadIdx.x] = 0;
}

// ------- fused: transpose x[B][L][D] -> xt[B][D][L]  AND split x -> sp0 -------
__global__ void k_prep_x(const float* __restrict__ x){
    __shared__ float tile[32][33];
    int b  = blockIdx.z;
    int l0 = blockIdx.x * 32, d0 = blockIdx.y * 32;
    int tx = threadIdx.x, ty = threadIdx.y;      // (32,8)
    #pragma unroll
    for (int r = 0; r < 4; r++){
        int l = l0 + ty + r*8;
        tile[ty + r*8][tx] = x[((size_t)b*LL + l)*DD + d0 + tx];   // tile[l_loc][d_loc]
    }
    __syncthreads();
    #pragma unroll
    for (int r = 0; r < 4; r++){
        int d = d0 + ty + r*8;
        g_xt[((size_t)b*DD + d)*LL + l0 + tx] = tile[tx][ty + r*8];
    }
    int tid = ty*32 + tx;
    #pragma unroll
    for (int i = 0; i < 2; i++){
        int t = tid + i*256;                     // 512 tasks: l (32) x pair (16)
        int l = t >> 4, p = t & 15;
        uint32_t hp, lp;
        cvt2_split(tile[l][2*p], tile[l][2*p+1], hp, lp);
        size_t o = ((size_t)b*LL + l0 + l)*128 + (d0 >> 1) + p;
        g_sp0_hi[o] = hp;
        g_sp0_lo[o] = lp;
    }
}

// ---------------- prep: split conv weights to bf16 hi/lo packed pairs ----------
__global__ void k_prep_w(const float* __restrict__ cw){
    int idx = blockIdx.x * 256 + threadIdx.x;    // 294912 total
    int layer = idx / 98304;
    int rem   = idx % 98304;
    int tap   = rem / 32768;
    int rem2  = rem % 32768;
    int dout  = rem2 >> 7;
    int p     = rem2 & 127;
    float a = cw[(((size_t)layer*256 + dout)*256 + 2*p    )*3 + tap];
    float b = cw[(((size_t)layer*256 + dout)*256 + 2*p + 1)*3 + tap];
    uint32_t hp, lp;
    cvt2_split(a, b, hp, lp);
    size_t o = ((size_t)(layer*3 + tap)*256 + dout)*128 + p;
    g_wsp_hi[o] = hp;
    g_wsp_lo[o] = lp;
}

// ======= tensor-core dilated conv (bf16 3-pass), cp.async pipeline ==============
#define CRS 20                                // u32 stride per SMEM row (mult of 4!)
#define CA_MAT (128*CRS)                      // 2560 u32 per A matrix
#define CB_MAT (136*CRS)                      // 2720 u32 per B matrix
#define CSTAGE (6*CA_MAT + 2*CB_MAT)          // 20800 u32
#define SMEM_CONV (2*CSTAGE*4)                // 166400 B

__global__ __launch_bounds__(512)
void k_conv_mma(const float* __restrict__ cb, int layer, int dil,
                int insel, int osplit, int outsel)
{
    int b     = blockIdx.z;
    int dout0 = blockIdx.y * 128;
    int l0    = blockIdx.x * 128;
    int W     = 128 + 2*dil;
    const uint32_t* in_hi = spin_hi(insel);
    const uint32_t* in_lo = spin_lo(insel);

    extern __shared__ uint32_t smc[];
    uint32_t smcb = (uint32_t)__cvta_generic_to_shared(smc);
    int tid  = threadIdx.x;
    int wid  = tid >> 5, lane = tid & 31;
    int wm   = wid >> 2, wn = wid & 3;        // warp grid 4x4, warp tile 32x32
    int g    = lane >> 2, t4 = lane & 3;
    int lrow = lane & 15;                     // ldmatrix row-within-16
    int lcol = (lane >> 4) << 4;              // ldmatrix col byte offset (0/16)

    float acc[2][4][4];
    #pragma unroll
    for (int i = 0; i < 2; i++)
        #pragma unroll
        for (int j = 0; j < 4; j++)
            #pragma unroll
            for (int k = 0; k < 4; k++) acc[i][j][k] = 0.f;

    auto load_chunk = [&](int ic, int stage){
        uint32_t stb = smcb + stage*(CSTAGE*4);
        int cbase = ic * 16;
        #pragma unroll
        for (int i = 0; i < 3; i++){
            int t   = tid + i*512;            // 1536 tasks (A)
            int tap = t >> 9;
            int rr  = (t >> 2) & 127;
            int q   = t & 3;
            size_t off = ((size_t)(layer*3 + tap)*256 + dout0 + rr)*128 + cbase + q*4;
            uint32_t dA = stb + (uint32_t)((tap*CA_MAT + rr*CRS + q*4)*4);
            CP_A16(dA,               g_wsp_hi + off);
            CP_A16(dA + 3*CA_MAT*4,  g_wsp_lo + off);
        }
        #pragma unroll
        for (int i = 0; i < 2; i++){
            int t = tid + i*512;              // up to W*4 tasks (B)
            if (t < W*4){
                int row = t >> 2, q = t & 3;
                int l = l0 - dil + row;
                int ok = (l >= 0 && l < LL);
                size_t off = ((size_t)b*LL + (ok ? l : 0))*128 + cbase + q*4;
                uint32_t sz = ok ? 16u : 0u;
                uint32_t dB = stb + (uint32_t)((6*CA_MAT + row*CRS + q*4)*4);
                CP_A16S(dB,            in_hi + off, sz);
                CP_A16S(dB + CB_MAT*4, in_lo + off, sz);
            }
        }
    };

    load_chunk(0, 0);
    CP_COMMIT();
    CP_WAIT0();
    __syncthreads();

    for (int ic = 0; ic < 8; ic++){
        int stage = ic & 1;
        if (ic + 1 < 8){ load_chunk(ic + 1, stage ^ 1); CP_COMMIT(); }

        uint32_t stb = smcb + stage*(CSTAGE*4);
        #pragma unroll
        for (int s = 0; s < 2; s++){
            #pragma unroll
            for (int tap = 0; tap < 3; tap++){
                uint32_t ah[2][4], al[2][4], bqh[2][4], bql[2][4];
                #pragma unroll
                for (int mt = 0; mt < 2; mt++){
                    uint32_t off = (uint32_t)(((wm*32 + mt*16 + lrow)*CRS + s*8)*4) + lcol;
                    LDMX4(ah[mt], stb + tap*(CA_MAT*4) + off);
                    LDMX4(al[mt], stb + (3+tap)*(CA_MAT*4) + off);
                }
                int shift = tap*dil;
                #pragma unroll
                for (int p = 0; p < 2; p++){
                    uint32_t off = (uint32_t)(((wn*32 + p*16 + shift + lrow)*CRS + s*8)*4) + lcol;
                    LDMX4(bqh[p], stb + 6*(CA_MAT*4) + off);
                    LDMX4(bql[p], stb + 6*(CA_MAT*4) + CB_MAT*4 + off);
                }
                #pragma unroll
                for (int mt = 0; mt < 2; mt++)
                    #pragma unroll
                    for (int nt = 0; nt < 4; nt++){
                        int p = nt >> 1, j = nt & 1;
                        uint32_t bh2[2] = { bqh[p][j], bqh[p][2+j] };
                        uint32_t bl2[2] = { bql[p][j], bql[p][2+j] };
                        mma16816_bf(acc[mt][nt], ah[mt], bh2);
                        mma16816_bf(acc[mt][nt], al[mt], bh2);
                        mma16816_bf(acc[mt][nt], ah[mt], bl2);
                    }
            }
        }
        if (ic + 1 < 8){
            CP_WAIT0();
            __syncthreads();
        }
    }

    if (!osplit){
        // fp32 epilogue (conv2 -> router)
        #pragma unroll
        for (int mt = 0; mt < 2; mt++){
            int r0 = dout0 + wm*32 + mt*16 + g;
            float bv0 = cb[layer*DD + r0];
            float bv1 = cb[layer*DD + r0 + 8];
            #pragma unroll
            for (int nt = 0; nt < 4; nt++){
                int c = l0 + wn*32 + nt*8 + 2*t4;
                float2 o;
                o.x = gelu_f(acc[mt][nt][0] + bv0);
                o.y = gelu_f(acc[mt][nt][1] + bv0);
                *(float2*)&g_bufA[((size_t)b*DD + r0)*LL + c] = o;
                o.x = gelu_f(acc[mt][nt][2] + bv1);
                o.y = gelu_f(acc[mt][nt][3] + bv1);
                *(float2*)&g_bufA[((size_t)b*DD + r0 + 8)*LL + c] = o;
            }
        }
    } else {
        // split epilogue: stage gelu'd fp32 tile in SMEM, emit bf16 hi/lo [l][dout/2]
        uint32_t* out_hi = spout_hi(outsel);
        uint32_t* out_lo = spout_lo(outsel);
        __syncthreads();                          // all frag reads done
        float* sOut = (float*)smc;                // 128 x 129 floats = 66048 B
        #pragma unroll
        for (int mt = 0; mt < 2; mt++){
            int rl = wm*32 + mt*16 + g;           // local dout
            float bv0 = cb[layer*DD + dout0 + rl];
            float bv1 = cb[layer*DD + dout0 + rl + 8];
            #pragma unroll
            for (int nt = 0; nt < 4; nt++){
                int cl = wn*32 + nt*8 + 2*t4;     // local l
                sOut[rl*129 + cl]       = gelu_f(acc[mt][nt][0] + bv0);
                sOut[rl*129 + cl + 1]   = gelu_f(acc[mt][nt][1] + bv0);
                sOut[(rl+8)*129 + cl]   = gelu_f(acc[mt][nt][2] + bv1);
                sOut[(rl+8)*129 + cl+1] = gelu_f(acc[mt][nt][3] + bv1);
            }
        }
        __syncthreads();
        #pragma unroll
        for (int i = 0; i < 16; i++){             // 8192 (l, pair) tasks
            int t = tid + i*512;
            int l = t >> 6, p = t & 63;
            uint32_t hp, lp;
            cvt2_split(sOut[(2*p)*129 + l], sOut[(2*p+1)*129 + l], hp, lp);
            size_t o = ((size_t)b*LL + l0 + l)*128 + (dout0 >> 1) + p;
            out_hi[o] = hp;
            out_lo[o] = lp;
        }
    }
}

// ---------------- router: logits -> sigmoid -> softmax -> top2 -> compaction -----
__global__ void k_router(const float* __restrict__ flw, const float* __restrict__ flb){
    __shared__ float srow[LL];
    __shared__ float slog[EE];
    int t = blockIdx.x;
    int tid = threadIdx.x;                       // 256
    const float* row = g_bufA + (size_t)t * LL;  // conv2 output
    for (int i = tid; i < LL; i += 256) srow[i] = row[i];
    __syncthreads();
    int w = tid >> 5, lane = tid & 31;
    float p = 0.f;
    for (int i = lane; i < LL; i += 32) p += srow[i] * flw[w*LL + i];
    #pragma unroll
    for (int o = 16; o > 0; o >>= 1) p += __shfl_down_sync(0xffffffffu, p, o);
    if (lane == 0) slog[w] = p + flb[w];
    __syncthreads();
    if (tid == 0){
        float s[EE], pr[EE], mx = -1e30f;
        #pragma unroll
        for (int e = 0; e < EE; e++){ s[e] = 1.f/(1.f + expf(-slog[e])); mx = fmaxf(mx, s[e]); }
        float sum = 0.f;
        #pragma unroll
        for (int e = 0; e < EE; e++){ pr[e] = expf(s[e] - mx); sum += pr[e]; }
        #pragma unroll
        for (int e = 0; e < EE; e++) pr[e] /= sum;
        int i0 = 0;
        #pragma unroll
        for (int e = 1; e < EE; e++) if (pr[e] > pr[i0]) i0 = e;
        int i1 = -1;
        #pragma unroll
        for (int e = 0; e < EE; e++){
            if (e == i0) continue;
            if (i1 < 0 || pr[e] > pr[i1]) i1 = e;
        }
        float gsum = pr[i0] + pr[i1];
        float g0 = pr[i0]/gsum, g1 = pr[i1]/gsum;
        int p0 = atomicAdd(&g_cnt[i0], 1);
        int p1 = atomicAdd(&g_cnt[i1], 1);
        g_idx[i0*NTOK + p0] = t;
        g_idx[i1*NTOK + p1] = t;
        g_tok_e[2*t]   = i0; g_tok_p[2*t]   = p0; g_tok_g[2*t]   = g0;
        g_tok_e[2*t+1] = i1; g_tok_p[2*t+1] = p1; g_tok_g[2*t+1] = g1;
    }
}

// ------------ compacted downsample (avg pool f=e+2), fp16-split output --------
__global__ void k_down(){
    int e = blockIdx.y;
    int i = blockIdx.x;
    if (i >= g_cnt[e]) return;
    int tok = g_idx[e*NTOK + i];
    int j = threadIdx.x;                         // 512
    int f = e + 2, len = c_len[e];
    float v = 0.f;
    if (j < len){
        const float* p = &g_xt[(size_t)tok*LL + j*f];
        for (int u = 0; u < f; u++) v += p[u];
        v /= (float)f;
    }
    float vn = __shfl_down_sync(0xffffffffu, v, 1);
    if (!(j & 1)){
        uint32_t hp, lp;
        cvt2_split_h(v, vn, hp, lp);
        size_t o = ((size_t)e*NTOK + i)*256 + (j >> 1);
        g_xes_hi[o] = hp;
        g_xes_lo[o] = lp;
    }
}

// ======= fp16 2-pass mma GEMM: cp.async A, reg-convert W, single sync/chunk =====
#define RS 20                      // b32 stride per row (MULT OF 4)
#define MAT_U32 (128*RS)           // 2560
#define STAGE_U32 (3*MAT_U32)      // Ahi, Alo, Whi
#define SMEM_MMA (2*STAGE_U32*4)   // 61440 B

__global__ __launch_bounds__(512)
void k_gemm_mma(const float* __restrict__ Wt, const float* __restrict__ bias,
                int absel, int lda32, int ldw, int osel, int NCfixed, int act)
{
    int e = blockIdx.z;
    int cnt = g_cnt[e];
    int m0 = blockIdx.y * 128;
    if (m0 >= cnt) return;
    int n0 = blockIdx.x * 128;
    int NC = NCfixed ? NCfixed : c_nc32[e];

    extern __shared__ uint32_t smu[];
    uint32_t smub = (uint32_t)__cvta_generic_to_shared(smu);
    const uint32_t* Ahi = asel_hi(absel) + ((size_t)e*NTOK + m0)*lda32;
    const uint32_t* Alo = asel_lo(absel) + ((size_t)e*NTOK + m0)*lda32;
    const float*    We  = Wt + ((size_t)e*HH + n0)*ldw;

    int tid  = threadIdx.x;
    int wid  = tid >> 5, lane = tid & 31;
    int wm   = wid >> 2, wn = wid & 3;           // warp grid 4x4, warp tile 32x32
    int g    = lane >> 2, t4 = lane & 3;
    int lrow = lane & 15;
    int lcol = (lane >> 4) << 4;

    float acc[2][4][4];
    #pragma unroll
    for (int i = 0; i < 2; i++)
        #pragma unroll
        for (int j = 0; j < 4; j++)
            #pragma unroll
            for (int k = 0; k < 4; k++) acc[i][j][k] = 0.f;

    auto load_A_async = [&](int ic, int stage){
        uint32_t stb = smub + stage*(STAGE_U32*4);
        #pragma unroll
        for (int i = 0; i < 2; i++){
            int t = tid + i*512;                 // 1024 tasks (Ahi, Alo)
            int matsel = t >> 9;
            int rem = t & 511;
            int r = rem >> 2, q = rem & 3;
            const uint32_t* src = (matsel ? Alo : Ahi) + (size_t)r*lda32 + ic*16 + q*4;
            uint32_t dst = stb + (uint32_t)((matsel*MAT_U32 + r*RS + q*4)*4);
            CP_A16(dst, src);
        }
    };
    auto load_store_W = [&](int ic, int stage){
        uint32_t* st = smu + stage*STAGE_U32;
        int k0 = ic * 32;
        #pragma unroll
        for (int i = 0; i < 2; i++){
            int t = tid + i*512;                 // 1024 float4 tasks (128 rows x 8)
            int r = t >> 3, q = t & 7;
            float4 v = *(const float4*)(We + (size_t)r*ldw + k0 + q*4);
            uint32_t hp[2];
            cvt4_hi_h(v, hp);
            uint32_t o = 2*MAT_U32 + r*RS + q*2;
            st[o] = hp[0]; st[o+1] = hp[1];
        }
    };

    load_A_async(0, 0);
    CP_COMMIT();
    load_store_W(0, 0);
    CP_WAIT0();
    __syncthreads();

    for (int ic = 0; ic < NC; ic++){
        int stage = ic & 1;
        if (ic + 1 < NC){
            load_A_async(ic + 1, stage ^ 1);     // async, no regs
            CP_COMMIT();
            load_store_W(ic + 1, stage ^ 1);     // stage^1 readers done at prior sync
        }

        uint32_t stb = smub + stage*(STAGE_U32*4);
        #pragma unroll
        for (int s = 0; s < 2; s++){
            uint32_t ah[2][4], al[2][4], wq[2][4];
            #pragma unroll
            for (int mt = 0; mt < 2; mt++){
                uint32_t off = (uint32_t)(((wm*32 + mt*16 + lrow)*RS + s*8)*4) + lcol;
                LDMX4(ah[mt], stb + off);
                LDMX4(al[mt], stb + MAT_U32*4 + off);
            }
            #pragma unroll
            for (int p = 0; p < 2; p++){
                uint32_t off = (uint32_t)(((wn*32 + p*16 + lrow)*RS + s*8)*4) + lcol;
                LDMX4(wq[p], stb + 2*(MAT_U32*4) + off);
            }
            #pragma unroll
            for (int mt = 0; mt < 2; mt++)
                #pragma unroll
                for (int nt = 0; nt < 4; nt++){
                    int p = nt >> 1, j = nt & 1;
                    uint32_t wh2[2] = { wq[p][j], wq[p][2+j] };
                    mma16816_h(acc[mt][nt], ah[mt], wh2);
                    mma16816_h(acc[mt][nt], al[mt], wh2);
                }
        }
        if (ic + 1 < NC){
            CP_WAIT0();
            __syncthreads();
        }
    }

    if (osel == 3){
        float* C = g_h1 + (size_t)e*NTOK*HH;
        #pragma unroll
        for (int mt = 0; mt < 2; mt++){
            #pragma unroll
            for (int nt = 0; nt < 4; nt++){
                int col = n0 + wn*32 + nt*8 + 2*t4;
                float b0v = bias[e*HH + col], b1v = bias[e*HH + col + 1];
                int r0 = m0 + wm*32 + mt*16 + g;
                int r1 = r0 + 8;
                float2 o;
                if (r0 < cnt){
                    o.x = acc[mt][nt][0] + b0v; o.y = acc[mt][nt][1] + b1v;
                    *(float2*)&C[(size_t)r0*HH + col] = o;
                }
                if (r1 < cnt){
                    o.x = acc[mt][nt][2] + b0v; o.y = acc[mt][nt][3] + b1v;
                    *(float2*)&C[(size_t)r1*HH + col] = o;
                }
            }
        }
    } else {
        uint32_t* Chi = osel_hi(osel) + (size_t)e*NTOK*512;
        uint32_t* Clo = osel_lo(osel) + (size_t)e*NTOK*512;
        #pragma unroll
        for (int mt = 0; mt < 2; mt++){
            #pragma unroll
            for (int nt = 0; nt < 4; nt++){
                int col = n0 + wn*32 + nt*8 + 2*t4;
                float b0v = bias[e*HH + col], b1v = bias[e*HH + col + 1];
                int r0 = m0 + wm*32 + mt*16 + g;
                int r1 = r0 + 8;
                uint32_t hp, lp;
                if (r0 < cnt){
                    float ox = acc[mt][nt][0] + b0v, oy = acc[mt][nt][1] + b1v;
                    if (act){ ox = gelu_f(ox); oy = gelu_f(oy); }
                    cvt2_split_h(ox, oy, hp, lp);
                    Chi[(size_t)r0*512 + (col>>1)] = hp;
                    Clo[(size_t)r0*512 + (col>>1)] = lp;
                }
                if (r1 < cnt){
                    float ox = acc[mt][nt][2] + b0v, oy = acc[mt][nt][3] + b1v;
                    if (act){ ox = gelu_f(ox); oy = gelu_f(oy); }
                    cvt2_split_h(ox, oy, hp, lp);
                    Chi[(size_t)r1*512 + (col>>1)] = hp;
                    Clo[(size_t)r1*512 + (col>>1)] = lp;
                }
            }
        }
    }
}

// ---------------- gated combine: out[b,o,d] = g0*h3[e0,p0,o] + g1*h3[e1,p1,o] ----
__global__ void k_combine(float* __restrict__ out){
    int o0 = blockIdx.x * 4;
    int b  = blockIdx.y;
    int d  = threadIdx.x;                        // 256
    int t  = b*DD + d;
    int e0 = g_tok_e[2*t],   p0 = g_tok_p[2*t];   float g0 = g_tok_g[2*t];
    int e1 = g_tok_e[2*t+1], p1 = g_tok_p[2*t+1]; float g1 = g_tok_g[2*t+1];
    float4 a = *(const float4*)&g_h1[((size_t)e0*NTOK + p0)*HH + o0];  // h3 in g_h1
    float4 c = *(const float4*)&g_h1[((size_t)e1*NTOK + p1)*HH + o0];
    size_t base = ((size_t)b*HH + o0)*DD + d;
    out[base + 0*DD] = g0*a.x + g1*c.x;
    out[base + 1*DD] = g0*a.y + g1*c.y;
    out[base + 2*DD] = g0*a.z + g1*c.z;
    out[base + 3*DD] = g0*a.w + g1*c.w;
}

// ---------------- launch ----------------
extern "C" void kernel_launch(void* const* d_in, const int* in_sizes, int n_in,
                              void* d_out, int out_size){
    const float* x       = (const float*)d_in[0];
    const float* conv_ws = (const float*)d_in[1];
    const float* conv_bs = (const float*)d_in[2];
    const float* fl_w    = (const float*)d_in[3];
    const float* fl_b    = (const float*)d_in[4];
    const float* w1      = (const float*)d_in[5];
    const float* b1      = (const float*)d_in[6];
    const float* w2      = (const float*)d_in[7];
    const float* b2      = (const float*)d_in[8];
    const float* w3      = (const float*)d_in[9];
    const float* b3      = (const float*)d_in[10];
    float* out = (float*)d_out;
    (void)in_sizes; (void)n_in; (void)out_size;

    cudaFuncSetAttribute(k_gemm_mma, cudaFuncAttributeMaxDynamicSharedMemorySize, SMEM_MMA);
    cudaFuncSetAttribute(k_conv_mma, cudaFuncAttributeMaxDynamicSharedMemorySize, SMEM_CONV);

    k_init<<<1, 32>>>();
    k_prep_x<<<dim3(32, 8, BB), dim3(32, 8)>>>(x);   // fused transpose + split
    k_prep_w<<<1152, 256>>>(conv_ws);

    // router convs on tensor cores (bf16 3-pass), cp.async pipeline
    k_conv_mma<<<dim3(8, 2, BB), 512, SMEM_CONV>>>(conv_bs, 0, 1, /*in*/0, /*osplit*/1, /*out*/1);
    k_conv_mma<<<dim3(8, 2, BB), 512, SMEM_CONV>>>(conv_bs, 1, 2, /*in*/1, /*osplit*/1, /*out*/0);
    k_conv_mma<<<dim3(8, 2, BB), 512, SMEM_CONV>>>(conv_bs, 2, 4, /*in*/0, /*osplit*/0, /*out*/0);

    k_router<<<NTOK, 256>>>(fl_w, fl_b);
    k_down  <<<dim3(NTOK, EE), 512>>>();

    // expert GEMMs: fp16 2-pass, cp.async A + reg-convert W, single sync/chunk
    k_gemm_mma<<<dim3(8, 16, EE), 512, SMEM_MMA>>>(w1, b1, /*A*/0, 256, 512,  /*C*/1, 0,  1); // xes -> h1s
    k_gemm_mma<<<dim3(8, 16, EE), 512, SMEM_MMA>>>(w2, b2, /*A*/1, 512, 1024, /*C*/2, 32, 1); // h1s -> h2s
    k_gemm_mma<<<dim3(8, 16, EE), 512, SMEM_MMA>>>(w3, b3, /*A*/2, 512, 1024, /*C*/3, 32, 0); // h2s -> h3 (fp32)

    k_combine<<<dim3(256, BB), 256>>>(out);
}

// round 17
// speedup vs baseline: 1.1282x; 1.1282x over previous
#include <cuda_runtime.h>
#include <cuda_bf16.h>
#include <cuda_fp16.h>
#include <math.h>
#include <stdint.h>

// Problem constants
#define BB 8
#define LL 1024
#define DD 256
#define EE 8
#define HH 1024
#define LMAXC 512
#define NTOK (BB*DD)   // 2048 tokens (b,d)

// ---------------- scratch (__device__ globals; no allocations) ----------------
__device__ float g_xt  [BB*DD*LL];        // x transposed [B][D][L] (for k_down)
__device__ float g_bufA[BB*DD*LL];        // conv2 fp32 output (router input)
__device__ float g_h1  [EE*NTOK*HH];      // h3 fp32 (combine input)
__device__ int   g_cnt [EE];
__device__ int   g_idx [EE*NTOK];
__device__ int   g_tok_e[NTOK*2];
__device__ int   g_tok_p[NTOK*2];
__device__ float g_tok_g[NTOK*2];
// conv path: bf16 split ping-pong [b][l][din/2]
__device__ uint32_t g_wsp_hi[3*3*256*128];   // [layer][tap][dout][din/2]
__device__ uint32_t g_wsp_lo[3*3*256*128];
__device__ uint32_t g_sp0_hi[BB*LL*128];
__device__ uint32_t g_sp0_lo[BB*LL*128];
__device__ uint32_t g_sp1_hi[BB*LL*128];
__device__ uint32_t g_sp1_lo[BB*LL*128];
// expert path: fp16 split activations
__device__ uint32_t g_xes_hi[EE*NTOK*256];   // [e][i][LMAXC/2]
__device__ uint32_t g_xes_lo[EE*NTOK*256];
__device__ uint32_t g_h1s_hi[EE*NTOK*512];   // [e][i][HH/2]
__device__ uint32_t g_h1s_lo[EE*NTOK*512];
__device__ uint32_t g_h2s_hi[EE*NTOK*512];
__device__ uint32_t g_h2s_lo[EE*NTOK*512];

__constant__ int c_len [EE] = {512,341,256,204,170,146,128,113};
__constant__ int c_nc32[EE] = {16,11,8,7,6,5,4,4};   // ceil(len/32) K-chunks, layer 1

__device__ __forceinline__ float gelu_f(float x){
    return 0.5f * x * (1.0f + erff(x * 0.70710678118654752f));
}

// ---- bf16 split (conv/router path) ----
__device__ __forceinline__ void cvt2_split(float a, float b, uint32_t& hp, uint32_t& lp){
    __nv_bfloat16 h0 = __float2bfloat16_rn(a);
    __nv_bfloat16 h1 = __float2bfloat16_rn(b);
    __nv_bfloat16 l0 = __float2bfloat16_rn(a - __bfloat162float(h0));
    __nv_bfloat16 l1 = __float2bfloat16_rn(b - __bfloat162float(h1));
    hp = (uint32_t)__bfloat16_as_ushort(h0) | ((uint32_t)__bfloat16_as_ushort(h1) << 16);
    lp = (uint32_t)__bfloat16_as_ushort(l0) | ((uint32_t)__bfloat16_as_ushort(l1) << 16);
}
// ---- fp16 split (expert path) ----
__device__ __forceinline__ void cvt2_split_h(float a, float b, uint32_t& hp, uint32_t& lp){
    __half h0 = __float2half_rn(a);
    __half h1 = __float2half_rn(b);
    __half l0 = __float2half_rn(a - __half2float(h0));
    __half l1 = __float2half_rn(b - __half2float(h1));
    hp = (uint32_t)__half_as_ushort(h0) | ((uint32_t)__half_as_ushort(h1) << 16);
    lp = (uint32_t)__half_as_ushort(l0) | ((uint32_t)__half_as_ushort(l1) << 16);
}
__device__ __forceinline__ void cvt4_hi_h(float4 v, uint32_t* hp){
    __half h0 = __float2half_rn(v.x);
    __half h1 = __float2half_rn(v.y);
    __half h2 = __float2half_rn(v.z);
    __half h3 = __float2half_rn(v.w);
    hp[0] = (uint32_t)__half_as_ushort(h0) | ((uint32_t)__half_as_ushort(h1) << 16);
    hp[1] = (uint32_t)__half_as_ushort(h2) | ((uint32_t)__half_as_ushort(h3) << 16);
}

__device__ __forceinline__ void mma16816_bf(float* d, const uint32_t* a, const uint32_t* b){
    asm volatile(
        "mma.sync.aligned.m16n8k16.row.col.f32.bf16.bf16.f32 "
        "{%0,%1,%2,%3}, {%4,%5,%6,%7}, {%8,%9}, {%0,%1,%2,%3};"
        : "+f"(d[0]), "+f"(d[1]), "+f"(d[2]), "+f"(d[3])
        : "r"(a[0]), "r"(a[1]), "r"(a[2]), "r"(a[3]), "r"(b[0]), "r"(b[1]));
}
__device__ __forceinline__ void mma16816_h(float* d, const uint32_t* a, const uint32_t* b){
    asm volatile(
        "mma.sync.aligned.m16n8k16.row.col.f32.f16.f16.f32 "
        "{%0,%1,%2,%3}, {%4,%5,%6,%7}, {%8,%9}, {%0,%1,%2,%3};"
        : "+f"(d[0]), "+f"(d[1]), "+f"(d[2]), "+f"(d[3])
        : "r"(a[0]), "r"(a[1]), "r"(a[2]), "r"(a[3]), "r"(b[0]), "r"(b[1]));
}
// 4-fragment shared load (GEMM only; conv measured faster with scalar LDS)
#define LDMX4(r, a) \
    asm volatile("ldmatrix.sync.aligned.m8n8.x4.shared.b16 {%0,%1,%2,%3}, [%4];" \
        : "=r"((r)[0]), "=r"((r)[1]), "=r"((r)[2]), "=r"((r)[3]) : "r"(a))

// pointer selectors (host can't take addresses of __device__ globals)
__device__ __forceinline__ const uint32_t* spin_hi(int s){ return s ? g_sp1_hi : g_sp0_hi; }
__device__ __forceinline__ const uint32_t* spin_lo(int s){ return s ? g_sp1_lo : g_sp0_lo; }
__device__ __forceinline__ uint32_t* spout_hi(int s){ return s ? g_sp1_hi : g_sp0_hi; }
__device__ __forceinline__ uint32_t* spout_lo(int s){ return s ? g_sp1_lo : g_sp0_lo; }
__device__ __forceinline__ const uint32_t* asel_hi(int s){ return s==0 ? g_xes_hi : (s==1 ? g_h1s_hi : g_h2s_hi); }
__device__ __forceinline__ const uint32_t* asel_lo(int s){ return s==0 ? g_xes_lo : (s==1 ? g_h1s_lo : g_h2s_lo); }
__device__ __forceinline__ uint32_t* osel_hi(int s){ return s==1 ? g_h1s_hi : g_h2s_hi; }
__device__ __forceinline__ uint32_t* osel_lo(int s){ return s==1 ? g_h1s_lo : g_h2s_lo; }

// ---------------- init ----------------
__global__ void k_init(){
    if (threadIdx.x < EE) g_cnt[threadIdx.x] = 0;
}

// ------- fused: transpose x[B][L][D] -> xt[B][D][L]  AND split x -> sp0 -------
__global__ void k_prep_x(const float* __restrict__ x){
    __shared__ float tile[32][33];
    int b  = blockIdx.z;
    int l0 = blockIdx.x * 32, d0 = blockIdx.y * 32;
    int tx = threadIdx.x, ty = threadIdx.y;      // (32,8)
    #pragma unroll
    for (int r = 0; r < 4; r++){
        int l = l0 + ty + r*8;
        tile[ty + r*8][tx] = x[((size_t)b*LL + l)*DD + d0 + tx];   // tile[l_loc][d_loc]
    }
    __syncthreads();
    #pragma unroll
    for (int r = 0; r < 4; r++){
        int d = d0 + ty + r*8;
        g_xt[((size_t)b*DD + d)*LL + l0 + tx] = tile[tx][ty + r*8];
    }
    int tid = ty*32 + tx;
    #pragma unroll
    for (int i = 0; i < 2; i++){
        int t = tid + i*256;                     // 512 tasks: l (32) x pair (16)
        int l = t >> 4, p = t & 15;
        uint32_t hp, lp;
        cvt2_split(tile[l][2*p], tile[l][2*p+1], hp, lp);
        size_t o = ((size_t)b*LL + l0 + l)*128 + (d0 >> 1) + p;
        g_sp0_hi[o] = hp;
        g_sp0_lo[o] = lp;
    }
}

// ---------------- prep: split conv weights to bf16 hi/lo packed pairs ----------
__global__ void k_prep_w(const float* __restrict__ cw){
    int idx = blockIdx.x * 256 + threadIdx.x;    // 294912 total
    int layer = idx / 98304;
    int rem   = idx % 98304;
    int tap   = rem / 32768;
    int rem2  = rem % 32768;
    int dout  = rem2 >> 7;
    int p     = rem2 & 127;
    float a = cw[(((size_t)layer*256 + dout)*256 + 2*p    )*3 + tap];
    float b = cw[(((size_t)layer*256 + dout)*256 + 2*p + 1)*3 + tap];
    uint32_t hp, lp;
    cvt2_split(a, b, hp, lp);
    size_t o = ((size_t)(layer*3 + tap)*256 + dout)*128 + p;
    g_wsp_hi[o] = hp;
    g_wsp_lo[o] = lp;
}

// ======= tensor-core dilated conv (bf16 3-pass), 512 threads, scalar LDS frags ===
// (R10 mainloop: measured 40.7us/layer vs 42.4 with ldmatrix — conv keeps scalar)
#define CRS 20                                // u32 stride per SMEM row (mult of 4!)
#define CA_MAT (128*CRS)                      // 2560 u32 per A matrix
#define CB_MAT (136*CRS)                      // 2720 u32 per B matrix
#define CSTAGE (6*CA_MAT + 2*CB_MAT)          // 20800 u32
#define SMEM_CONV (2*CSTAGE*4)                // 166400 B

__global__ __launch_bounds__(512)
void k_conv_mma(const float* __restrict__ cb, int layer, int dil,
                int insel, int osplit, int outsel)
{
    int b     = blockIdx.z;
    int dout0 = blockIdx.y * 128;
    int l0    = blockIdx.x * 128;
    int W     = 128 + 2*dil;
    const uint32_t* in_hi = spin_hi(insel);
    const uint32_t* in_lo = spin_lo(insel);

    extern __shared__ uint32_t smc[];
    int tid  = threadIdx.x;
    int wid  = tid >> 5, lane = tid & 31;
    int wm   = wid >> 2, wn = wid & 3;        // warp grid 4x4, warp tile 32x32
    int g    = lane >> 2, t4 = lane & 3;

    float acc[2][4][4];
    #pragma unroll
    for (int i = 0; i < 2; i++)
        #pragma unroll
        for (int j = 0; j < 4; j++)
            #pragma unroll
            for (int k = 0; k < 4; k++) acc[i][j][k] = 0.f;

    uint4 pa_h[3], pa_l[3], pb_h[2], pb_l[2];

    auto prefetch = [&](int ic){
        int cbase = ic * 16;                  // pair-column base for this chunk
        #pragma unroll
        for (int i = 0; i < 3; i++){
            int t   = tid + i*512;            // 1536 uint4 tasks (A)
            int tap = t >> 9;
            int rr  = (t >> 2) & 127;
            int q   = t & 3;
            size_t off = ((size_t)(layer*3 + tap)*256 + dout0 + rr)*128 + cbase + q*4;
            pa_h[i] = *(const uint4*)(g_wsp_hi + off);
            pa_l[i] = *(const uint4*)(g_wsp_lo + off);
        }
        #pragma unroll
        for (int i = 0; i < 2; i++){
            int t = tid + i*512;              // up to W*4 uint4 tasks (B)
            pb_h[i] = make_uint4(0,0,0,0);
            pb_l[i] = make_uint4(0,0,0,0);
            if (t < W*4){
                int row = t >> 2, q = t & 3;
                int l = l0 - dil + row;
                if (l >= 0 && l < LL){
                    size_t off = ((size_t)b*LL + l)*128 + cbase + q*4;
                    pb_h[i] = *(const uint4*)(in_hi + off);
                    pb_l[i] = *(const uint4*)(in_lo + off);
                }
            }
        }
    };
    auto commit = [&](int stage){
        uint32_t* st = smc + stage*CSTAGE;
        #pragma unroll
        for (int i = 0; i < 3; i++){
            int t   = tid + i*512;
            int tap = t >> 9;
            int rr  = (t >> 2) & 127;
            int q   = t & 3;
            uint32_t o = tap*CA_MAT + rr*CRS + q*4;
            *(uint4*)(st + o)            = pa_h[i];
            *(uint4*)(st + 3*CA_MAT + o) = pa_l[i];
        }
        #pragma unroll
        for (int i = 0; i < 2; i++){
            int t = tid + i*512;
            if (t < W*4){
                int row = t >> 2, q = t & 3;
                uint32_t o = 6*CA_MAT + row*CRS + q*4;
                *(uint4*)(st + o)          = pb_h[i];
                *(uint4*)(st + CB_MAT + o) = pb_l[i];
            }
        }
    };

    prefetch(0);
    commit(0);
    __syncthreads();

    for (int ic = 0; ic < 8; ic++){
        int stage = ic & 1;
        if (ic + 1 < 8) prefetch(ic + 1);

        const uint32_t* st = smc + stage*CSTAGE;
        #pragma unroll
        for (int s = 0; s < 2; s++){
            #pragma unroll
            for (int tap = 0; tap < 3; tap++){
                const uint32_t* Ah = st + tap*CA_MAT;
                const uint32_t* Al = st + 3*CA_MAT + tap*CA_MAT;
                const uint32_t* Bh = st + 6*CA_MAT;
                const uint32_t* Bl = st + 6*CA_MAT + CB_MAT;
                uint32_t ah[2][4], al[2][4], bh[4][2], bl[4][2];
                #pragma unroll
                for (int mt = 0; mt < 2; mt++){
                    int row = wm*32 + mt*16 + g;
                    uint32_t o0 = row*CRS + s*8 + t4;
                    ah[mt][0] = Ah[o0];           ah[mt][1] = Ah[o0 + 8*CRS];
                    ah[mt][2] = Ah[o0 + 4];       ah[mt][3] = Ah[o0 + 8*CRS + 4];
                    al[mt][0] = Al[o0];           al[mt][1] = Al[o0 + 8*CRS];
                    al[mt][2] = Al[o0 + 4];       al[mt][3] = Al[o0 + 8*CRS + 4];
                }
                int shift = tap*dil;
                #pragma unroll
                for (int nt = 0; nt < 4; nt++){
                    int row = wn*32 + nt*8 + g + shift;
                    uint32_t o0 = row*CRS + s*8 + t4;
                    bh[nt][0] = Bh[o0]; bh[nt][1] = Bh[o0 + 4];
                    bl[nt][0] = Bl[o0]; bl[nt][1] = Bl[o0 + 4];
                }
                #pragma unroll
                for (int mt = 0; mt < 2; mt++)
                    #pragma unroll
                    for (int nt = 0; nt < 4; nt++){
                        mma16816_bf(acc[mt][nt], ah[mt], bh[nt]);
                        mma16816_bf(acc[mt][nt], al[mt], bh[nt]);
                        mma16816_bf(acc[mt][nt], ah[mt], bl[nt]);
                    }
            }
        }
        if (ic + 1 < 8){
            __syncthreads();
            commit(stage ^ 1);
            __syncthreads();
        }
    }

    if (!osplit){
        // fp32 epilogue (conv2 -> router)
        #pragma unroll
        for (int mt = 0; mt < 2; mt++){
            int r0 = dout0 + wm*32 + mt*16 + g;
            float bv0 = cb[layer*DD + r0];
            float bv1 = cb[layer*DD + r0 + 8];
            #pragma unroll
            for (int nt = 0; nt < 4; nt++){
                int c = l0 + wn*32 + nt*8 + 2*t4;
                float2 o;
                o.x = gelu_f(acc[mt][nt][0] + bv0);
                o.y = gelu_f(acc[mt][nt][1] + bv0);
                *(float2*)&g_bufA[((size_t)b*DD + r0)*LL + c] = o;
                o.x = gelu_f(acc[mt][nt][2] + bv1);
                o.y = gelu_f(acc[mt][nt][3] + bv1);
                *(float2*)&g_bufA[((size_t)b*DD + r0 + 8)*LL + c] = o;
            }
        }
    } else {
        // split epilogue: stage gelu'd fp32 tile in SMEM, emit bf16 hi/lo [l][dout/2]
        uint32_t* out_hi = spout_hi(outsel);
        uint32_t* out_lo = spout_lo(outsel);
        __syncthreads();                          // all frag reads done
        float* sOut = (float*)smc;                // 128 x 129 floats = 66048 B
        #pragma unroll
        for (int mt = 0; mt < 2; mt++){
            int rl = wm*32 + mt*16 + g;           // local dout
            float bv0 = cb[layer*DD + dout0 + rl];
            float bv1 = cb[layer*DD + dout0 + rl + 8];
            #pragma unroll
            for (int nt = 0; nt < 4; nt++){
                int cl = wn*32 + nt*8 + 2*t4;     // local l
                sOut[rl*129 + cl]       = gelu_f(acc[mt][nt][0] + bv0);
                sOut[rl*129 + cl + 1]   = gelu_f(acc[mt][nt][1] + bv0);
                sOut[(rl+8)*129 + cl]   = gelu_f(acc[mt][nt][2] + bv1);
                sOut[(rl+8)*129 + cl+1] = gelu_f(acc[mt][nt][3] + bv1);
            }
        }
        __syncthreads();
        #pragma unroll
        for (int i = 0; i < 16; i++){             // 8192 (l, pair) tasks
            int t = tid + i*512;
            int l = t >> 6, p = t & 63;
            uint32_t hp, lp;
            cvt2_split(sOut[(2*p)*129 + l], sOut[(2*p+1)*129 + l], hp, lp);
            size_t o = ((size_t)b*LL + l0 + l)*128 + (dout0 >> 1) + p;
            out_hi[o] = hp;
            out_lo[o] = lp;
        }
    }
}

// ---------------- router: logits -> sigmoid -> softmax -> top2 -> compaction -----
__global__ void k_router(const float* __restrict__ flw, const float* __restrict__ flb){
    __shared__ float srow[LL];
    __shared__ float slog[EE];
    int t = blockIdx.x;
    int tid = threadIdx.x;                       // 256
    const float* row = g_bufA + (size_t)t * LL;  // conv2 output
    for (int i = tid; i < LL; i += 256) srow[i] = row[i];
    __syncthreads();
    int w = tid >> 5, lane = tid & 31;
    float p = 0.f;
    for (int i = lane; i < LL; i += 32) p += srow[i] * flw[w*LL + i];
    #pragma unroll
    for (int o = 16; o > 0; o >>= 1) p += __shfl_down_sync(0xffffffffu, p, o);
    if (lane == 0) slog[w] = p + flb[w];
    __syncthreads();
    if (tid == 0){
        float s[EE], pr[EE], mx = -1e30f;
        #pragma unroll
        for (int e = 0; e < EE; e++){ s[e] = 1.f/(1.f + expf(-slog[e])); mx = fmaxf(mx, s[e]); }
        float sum = 0.f;
        #pragma unroll
        for (int e = 0; e < EE; e++){ pr[e] = expf(s[e] - mx); sum += pr[e]; }
        #pragma unroll
        for (int e = 0; e < EE; e++) pr[e] /= sum;
        int i0 = 0;
        #pragma unroll
        for (int e = 1; e < EE; e++) if (pr[e] > pr[i0]) i0 = e;
        int i1 = -1;
        #pragma unroll
        for (int e = 0; e < EE; e++){
            if (e == i0) continue;
            if (i1 < 0 || pr[e] > pr[i1]) i1 = e;
        }
        float gsum = pr[i0] + pr[i1];
        float g0 = pr[i0]/gsum, g1 = pr[i1]/gsum;
        int p0 = atomicAdd(&g_cnt[i0], 1);
        int p1 = atomicAdd(&g_cnt[i1], 1);
        g_idx[i0*NTOK + p0] = t;
        g_idx[i1*NTOK + p1] = t;
        g_tok_e[2*t]   = i0; g_tok_p[2*t]   = p0; g_tok_g[2*t]   = g0;
        g_tok_e[2*t+1] = i1; g_tok_p[2*t+1] = p1; g_tok_g[2*t+1] = g1;
    }
}

// ------------ compacted downsample (avg pool f=e+2), fp16-split output --------
__global__ void k_down(){
    int e = blockIdx.y;
    int i = blockIdx.x;
    if (i >= g_cnt[e]) return;
    int tok = g_idx[e*NTOK + i];
    int j = threadIdx.x;                         // 512
    int f = e + 2, len = c_len[e];
    float v = 0.f;
    if (j < len){
        const float* p = &g_xt[(size_t)tok*LL + j*f];
        for (int u = 0; u < f; u++) v += p[u];
        v /= (float)f;
    }
    float vn = __shfl_down_sync(0xffffffffu, v, 1);
    if (!(j & 1)){
        uint32_t hp, lp;
        cvt2_split_h(v, vn, hp, lp);
        size_t o = ((size_t)e*NTOK + i)*256 + (j >> 1);
        g_xes_hi[o] = hp;
        g_xes_lo[o] = lp;
    }
}

// ======= fp16 2-pass mma GEMM, 512 threads, ldmatrix frags (proven R11 config) ==
#define RS 20                      // b32 stride per row (MULT OF 4 for uint4 stores)
#define MAT_U32 (128*RS)           // 2560
#define STAGE_U32 (3*MAT_U32)      // Ahi, Alo, Whi
#define SMEM_MMA (2*STAGE_U32*4)   // 61440 B

__global__ __launch_bounds__(512)
void k_gemm_mma(const float* __restrict__ Wt, const float* __restrict__ bias,
                int absel, int lda32, int ldw, int osel, int NCfixed, int act)
{
    int e = blockIdx.z;
    int cnt = g_cnt[e];
    int m0 = blockIdx.y * 128;
    if (m0 >= cnt) return;
    int n0 = blockIdx.x * 128;
    int NC = NCfixed ? NCfixed : c_nc32[e];

    extern __shared__ uint32_t smu[];
    uint32_t smub = (uint32_t)__cvta_generic_to_shared(smu);
    const uint32_t* Ahi = asel_hi(absel) + ((size_t)e*NTOK + m0)*lda32;
    const uint32_t* Alo = asel_lo(absel) + ((size_t)e*NTOK + m0)*lda32;
    const float*    We  = Wt + ((size_t)e*HH + n0)*ldw;

    int tid  = threadIdx.x;
    int wid  = tid >> 5, lane = tid & 31;
    int wm   = wid >> 2, wn = wid & 3;           // warp grid 4x4, warp tile 32x32
    int g    = lane >> 2, t4 = lane & 3;
    int lrow = lane & 15;
    int lcol = (lane >> 4) << 4;

    float acc[2][4][4];
    #pragma unroll
    for (int i = 0; i < 2; i++)
        #pragma unroll
        for (int j = 0; j < 4; j++)
            #pragma unroll
            for (int k = 0; k < 4; k++) acc[i][j][k] = 0.f;

    uint4  pa[2];                                // A copies (hi/lo interleaved tasks)
    float4 pw[2];                                // W rows
    auto prefetch = [&](int ic){
        #pragma unroll
        for (int i = 0; i < 2; i++){
            int t = tid + i*512;                 // 1024 uint4 tasks
            int matsel = t >> 9;
            int rem = t & 511;
            int r = rem >> 2, q = rem & 3;
            const uint32_t* src = matsel ? Alo : Ahi;
            pa[i] = *(const uint4*)(src + (size_t)r*lda32 + ic*16 + q*4);
        }
        int k0 = ic * 32;
        #pragma unroll
        for (int i = 0; i < 2; i++){
            int t = tid + i*512;                 // 1024 float4 tasks
            int r = t >> 3, q = t & 7;
            pw[i] = *(const float4*)(We + (size_t)r*ldw + k0 + q*4);
        }
    };
    auto commit = [&](int stage){
        uint32_t* st = smu + stage*STAGE_U32;
        #pragma unroll
        for (int i = 0; i < 2; i++){
            int t = tid + i*512;
            int matsel = t >> 9;
            int rem = t & 511;
            int r = rem >> 2, q = rem & 3;
            *(uint4*)(st + matsel*MAT_U32 + r*RS + q*4) = pa[i];   // r*20 ≡ 0 mod 4 ✓
        }
        #pragma unroll
        for (int i = 0; i < 2; i++){
            int t = tid + i*512;
            int r = t >> 3, q = t & 7;
            uint32_t hp[2];
            cvt4_hi_h(pw[i], hp);
            uint32_t o = 2*MAT_U32 + r*RS + q*2;
            st[o] = hp[0]; st[o+1] = hp[1];
        }
    };

    prefetch(0);
    commit(0);
    __syncthreads();

    for (int ic = 0; ic < NC; ic++){
        int stage = ic & 1;
        if (ic + 1 < NC) prefetch(ic + 1);

        uint32_t stb = smub + stage*(STAGE_U32*4);
        #pragma unroll
        for (int s = 0; s < 2; s++){
            uint32_t ah[2][4], al[2][4], wq[2][4];
            #pragma unroll
            for (int mt = 0; mt < 2; mt++){
                uint32_t off = (uint32_t)(((wm*32 + mt*16 + lrow)*RS + s*8)*4) + lcol;
                LDMX4(ah[mt], stb + off);
                LDMX4(al[mt], stb + MAT_U32*4 + off);
            }
            #pragma unroll
            for (int p = 0; p < 2; p++){
                uint32_t off = (uint32_t)(((wn*32 + p*16 + lrow)*RS + s*8)*4) + lcol;
                LDMX4(wq[p], stb + 2*(MAT_U32*4) + off);
            }
            #pragma unroll
            for (int mt = 0; mt < 2; mt++)
                #pragma unroll
                for (int nt = 0; nt < 4; nt++){
                    int p = nt >> 1, j = nt & 1;
                    uint32_t wh2[2] = { wq[p][j], wq[p][2+j] };
                    mma16816_h(acc[mt][nt], ah[mt], wh2);
                    mma16816_h(acc[mt][nt], al[mt], wh2);
                }
        }
        if (ic + 1 < NC){
            __syncthreads();
            commit(stage ^ 1);
            __syncthreads();
        }
    }

    if (osel == 3){
        float* C = g_h1 + (size_t)e*NTOK*HH;
        #pragma unroll
        for (int mt = 0; mt < 2; mt++){
            #pragma unroll
            for (int nt = 0; nt < 4; nt++){
                int col = n0 + wn*32 + nt*8 + 2*t4;
                float b0v = bias[e*HH + col], b1v = bias[e*HH + col + 1];
                int r0 = m0 + wm*32 + mt*16 + g;
                int r1 = r0 + 8;
                float2 o;
                if (r0 < cnt){
                    o.x = acc[mt][nt][0] + b0v; o.y = acc[mt][nt][1] + b1v;
                    *(float2*)&C[(size_t)r0*HH + col] = o;
                }
                if (r1 < cnt){
                    o.x = acc[mt][nt][2] + b0v; o.y = acc[mt][nt][3] + b1v;
                    *(float2*)&C[(size_t)r1*HH + col] = o;
                }
            }
        }
    } else {
        uint32_t* Chi = osel_hi(osel) + (size_t)e*NTOK*512;
        uint32_t* Clo = osel_lo(osel) + (size_t)e*NTOK*512;
        #pragma unroll
        for (int mt = 0; mt < 2; mt++){
            #pragma unroll
            for (int nt = 0; nt < 4; nt++){
                int col = n0 + wn*32 + nt*8 + 2*t4;
                float b0v = bias[e*HH + col], b1v = bias[e*HH + col + 1];
                int r0 = m0 + wm*32 + mt*16 + g;
                int r1 = r0 + 8;
                uint32_t hp, lp;
                if (r0 < cnt){
                    float ox = acc[mt][nt][0] + b0v, oy = acc[mt][nt][1] + b1v;
                    if (act){ ox = gelu_f(ox); oy = gelu_f(oy); }
                    cvt2_split_h(ox, oy, hp, lp);
                    Chi[(size_t)r0*512 + (col>>1)] = hp;
                    Clo[(size_t)r0*512 + (col>>1)] = lp;
                }
                if (r1 < cnt){
                    float ox = acc[mt][nt][2] + b0v, oy = acc[mt][nt][3] + b1v;
                    if (act){ ox = gelu_f(ox); oy = gelu_f(oy); }
                    cvt2_split_h(ox, oy, hp, lp);
                    Chi[(size_t)r1*512 + (col>>1)] = hp;
                    Clo[(size_t)r1*512 + (col>>1)] = lp;
                }
            }
        }
    }
}

// ---------------- gated combine: out[b,o,d] = g0*h3[e0,p0,o] + g1*h3[e1,p1,o] ----
__global__ void k_combine(float* __restrict__ out){
    int o0 = blockIdx.x * 4;
    int b  = blockIdx.y;
    int d  = threadIdx.x;                        // 256
    int t  = b*DD + d;
    int e0 = g_tok_e[2*t],   p0 = g_tok_p[2*t];   float g0 = g_tok_g[2*t];
    int e1 = g_tok_e[2*t+1], p1 = g_tok_p[2*t+1]; float g1 = g_tok_g[2*t+1];
    float4 a = *(const float4*)&g_h1[((size_t)e0*NTOK + p0)*HH + o0];  // h3 in g_h1
    float4 c = *(const float4*)&g_h1[((size_t)e1*NTOK + p1)*HH + o0];
    size_t base = ((size_t)b*HH + o0)*DD + d;
    out[base + 0*DD] = g0*a.x + g1*c.x;
    out[base + 1*DD] = g0*a.y + g1*c.y;
    out[base + 2*DD] = g0*a.z + g1*c.z;
    out[base + 3*DD] = g0*a.w + g1*c.w;
}

// ---------------- launch ----------------
extern "C" void kernel_launch(void* const* d_in, const int* in_sizes, int n_in,
                              void* d_out, int out_size){
    const float* x       = (const float*)d_in[0];
    const float* conv_ws = (const float*)d_in[1];
    const float* conv_bs = (const float*)d_in[2];
    const float* fl_w    = (const float*)d_in[3];
    const float* fl_b    = (const float*)d_in[4];
    const float* w1      = (const float*)d_in[5];
    const float* b1      = (const float*)d_in[6];
    const float* w2      = (const float*)d_in[7];
    const float* b2      = (const float*)d_in[8];
    const float* w3      = (const float*)d_in[9];
    const float* b3      = (const float*)d_in[10];
    float* out = (float*)d_out;
    (void)in_sizes; (void)n_in; (void)out_size;

    cudaFuncSetAttribute(k_gemm_mma, cudaFuncAttributeMaxDynamicSharedMemorySize, SMEM_MMA);
    cudaFuncSetAttribute(k_conv_mma, cudaFuncAttributeMaxDynamicSharedMemorySize, SMEM_CONV);

    k_init<<<1, 32>>>();
    k_prep_x<<<dim3(32, 8, BB), dim3(32, 8)>>>(x);   // fused transpose + split
    k_prep_w<<<1152, 256>>>(conv_ws);

    // router convs on tensor cores (bf16 3-pass), scalar-LDS mainloop (R10 best)
    k_conv_mma<<<dim3(8, 2, BB), 512, SMEM_CONV>>>(conv_bs, 0, 1, /*in*/0, /*osplit*/1, /*out*/1);
    k_conv_mma<<<dim3(8, 2, BB), 512, SMEM_CONV>>>(conv_bs, 1, 2, /*in*/1, /*osplit*/1, /*out*/0);
    k_conv_mma<<<dim3(8, 2, BB), 512, SMEM_CONV>>>(conv_bs, 2, 4, /*in*/0, /*osplit*/0, /*out*/0);

    k_router<<<NTOK, 256>>>(fl_w, fl_b);
    k_down  <<<dim3(NTOK, EE), 512>>>();

    // expert GEMMs: fp16 2-pass, 128x128 tiles, ldmatrix frags (R11 best)
    k_gemm_mma<<<dim3(8, 16, EE), 512, SMEM_MMA>>>(w1, b1, /*A*/0, 256, 512,  /*C*/1, 0,  1); // xes -> h1s
    k_gemm_mma<<<dim3(8, 16, EE), 512, SMEM_MMA>>>(w2, b2, /*A*/1, 512, 1024, /*C*/2, 32, 1); // h1s -> h2s
    k_gemm_mma<<<dim3(8, 16, EE), 512, SMEM_MMA>>>(w3, b3, /*A*/2, 512, 1024, /*C*/3, 32, 0); // h2s -> h3 (fp32)

    k_combine<<<dim3(256, BB), 256>>>(out);
}